// round 2
// baseline (speedup 1.0000x reference)
#include <cuda_runtime.h>

#define N_NODES 100000
#define DIN     128
#define HDIM    64

// Scratch (device globals -- no allocation allowed in kernel_launch)
__device__ float g_deg[N_NODES];
__device__ float g_dis[N_NODES];
__device__ float g_s[N_NODES];
__device__ float g_t[N_NODES];
__device__ __align__(16) float g_w[DIN];
__device__ float g_c1;
__device__ float g_c2;

// ---------------------------------------------------------------------------
// K0: collapse weights.  u = W2 @ fc_w  (64),  w = W1 @ u  (128),
//     c1 = b1 . u,  c2 = b2 . fc_w + fc_b.    One block of 128 threads.
// ---------------------------------------------------------------------------
__global__ void k_setup(const float* __restrict__ W1, const float* __restrict__ b1,
                        const float* __restrict__ W2, const float* __restrict__ b2,
                        const float* __restrict__ fc_w, const float* __restrict__ fc_b) {
    __shared__ float u[HDIM];
    int t = threadIdx.x;
    if (t < HDIM) {
        float acc = 0.f;
        #pragma unroll 8
        for (int j = 0; j < HDIM; ++j) acc += W2[t * HDIM + j] * fc_w[j];
        u[t] = acc;
    }
    __syncthreads();
    if (t < DIN) {
        float acc = 0.f;
        #pragma unroll 8
        for (int j = 0; j < HDIM; ++j) acc += W1[t * HDIM + j] * u[j];
        g_w[t] = acc;
    }
    if (t == 0) {
        float c1 = 0.f, c2 = 0.f;
        for (int j = 0; j < HDIM; ++j) { c1 += b1[j] * u[j]; c2 += b2[j] * fc_w[j]; }
        g_c1 = c1;
        g_c2 = c2 + fc_b[0];
    }
}

// K1: deg init with self-loop weight 1
__global__ void k_deg_init(int n) {
    int i = blockIdx.x * blockDim.x + threadIdx.x;
    if (i < n) g_deg[i] = 1.0f;
}

// K2: deg[dst] += ew   (dst = edge_index row 1, int32)
__global__ void k_deg_acc(const int* __restrict__ dst,
                          const float* __restrict__ ew, int E, int n) {
    int e = blockIdx.x * blockDim.x + threadIdx.x;
    if (e >= E) return;
    unsigned d = (unsigned)dst[e];
    if (d < (unsigned)n) atomicAdd(&g_deg[d], ew[e]);
}

// K3: per node -- dis = rsqrt(deg); s = x . w; t = dis^2 * s + c1 (self-loop term of prop1)
// One warp per node: 128 floats = 32 lanes x float4.
__global__ void k_node(const float* __restrict__ x, int n) {
    int warp = (blockIdx.x * blockDim.x + threadIdx.x) >> 5;
    int lane = threadIdx.x & 31;
    if (warp >= n) return;
    const float4* xr = (const float4*)(x + (size_t)warp * DIN);
    float4 xv = xr[lane];
    float4 wv = ((const float4*)g_w)[lane];
    float acc = xv.x * wv.x + xv.y * wv.y + xv.z * wv.z + xv.w * wv.w;
    #pragma unroll
    for (int o = 16; o; o >>= 1) acc += __shfl_xor_sync(0xFFFFFFFFu, acc, o);
    if (lane == 0) {
        float deg = g_deg[warp];
        float dis = deg > 0.f ? rsqrtf(fmaxf(deg, 1e-12f)) : 0.f;
        g_dis[warp] = dis;
        g_s[warp]   = acc;
        g_t[warp]   = dis * dis * acc + g_c1;
    }
}

// K4: prop1   t[dst] += dis[src]*ew*dis[dst] * s[src]
__global__ void k_prop1(const int* __restrict__ ei,
                        const float* __restrict__ ew, int E, int n) {
    int e = blockIdx.x * blockDim.x + threadIdx.x;
    if (e >= E) return;
    unsigned s = (unsigned)ei[e];
    unsigned d = (unsigned)ei[(size_t)E + e];
    if (s >= (unsigned)n || d >= (unsigned)n) return;
    float nrm = g_dis[s] * ew[e] * g_dis[d];
    atomicAdd(&g_t[d], nrm * g_s[s]);
}

// K5: re-init s as prop2 accumulator: s[n] = dis^2 * t[n] + c2 (self-loop + collapsed biases)
__global__ void k_mid(int n) {
    int i = blockIdx.x * blockDim.x + threadIdx.x;
    if (i < n) {
        float dis = g_dis[i];
        g_s[i] = dis * dis * g_t[i] + g_c2;
    }
}

// K6: prop2   s[dst] += norm * t[src]
__global__ void k_prop2(const int* __restrict__ ei,
                        const float* __restrict__ ew, int E, int n) {
    int e = blockIdx.x * blockDim.x + threadIdx.x;
    if (e >= E) return;
    unsigned s = (unsigned)ei[e];
    unsigned d = (unsigned)ei[(size_t)E + e];
    if (s >= (unsigned)n || d >= (unsigned)n) return;
    float nrm = g_dis[s] * ew[e] * g_dis[d];
    atomicAdd(&g_s[d], nrm * g_t[s]);
}

// K7: out = rint(clip(s, 0, 10))   (rintf = round-half-even, matches jnp.round)
__global__ void k_out(float* __restrict__ out, int n) {
    int i = blockIdx.x * blockDim.x + threadIdx.x;
    if (i < n) out[i] = rintf(fminf(fmaxf(g_s[i], 0.f), 10.f));
}

extern "C" void kernel_launch(void* const* d_in, const int* in_sizes, int n_in,
                              void* d_out, int out_size) {
    const float* x    = (const float*)d_in[0];
    const int*   ei   = (const int*)d_in[1];    // int32 [2, E] (JAX x64 disabled)
    const float* ew   = (const float*)d_in[2];
    const float* W1   = (const float*)d_in[3];
    const float* b1   = (const float*)d_in[4];
    const float* W2   = (const float*)d_in[5];
    const float* b2   = (const float*)d_in[6];
    const float* fc_w = (const float*)d_in[7];
    const float* fc_b = (const float*)d_in[8];
    float*       out  = (float*)d_out;

    const int E = in_sizes[2];             // 1600000
    const int N = in_sizes[0] / DIN;       // 100000

    const int TB = 256;
    const int nb_nodes = (N + TB - 1) / TB;
    const int nb_edges = (E + TB - 1) / TB;
    const int nb_warps = ((N * 32) + TB - 1) / TB;   // 1 warp per node

    k_setup<<<1, 128>>>(W1, b1, W2, b2, fc_w, fc_b);
    k_deg_init<<<nb_nodes, TB>>>(N);
    k_deg_acc<<<nb_edges, TB>>>(ei + E, ew, E, N);
    k_node<<<nb_warps, TB>>>(x, N);
    k_prop1<<<nb_edges, TB>>>(ei, ew, E, N);
    k_mid<<<nb_nodes, TB>>>(N);
    k_prop2<<<nb_edges, TB>>>(ei, ew, E, N);
    k_out<<<nb_nodes, TB>>>(out, N);
}

// round 3
// speedup vs baseline: 1.0431x; 1.0431x over previous
#include <cuda_runtime.h>

#define N_NODES 100000
#define DIN     128
#define HDIM    64

// Scratch (device globals -- no allocation allowed in kernel_launch)
__device__ float g_deg[N_NODES];
__device__ float g_dis[N_NODES];
__device__ float g_s[N_NODES];
__device__ float g_t[N_NODES];
__device__ __align__(16) float g_w[DIN];
__device__ float g_c1;
__device__ float g_c2;

// ---------------------------------------------------------------------------
// K0: fused init.  All blocks: deg[i] = 1 (self-loop weight).
// Block 0 additionally collapses weights:
//   u = W2 @ fc_w (64), w = W1 @ u (128), c1 = b1.u, c2 = b2.fc_w + fc_b
// ---------------------------------------------------------------------------
__global__ void k_init(const float* __restrict__ W1, const float* __restrict__ b1,
                       const float* __restrict__ W2, const float* __restrict__ b2,
                       const float* __restrict__ fc_w, const float* __restrict__ fc_b,
                       int n) {
    int i = blockIdx.x * blockDim.x + threadIdx.x;
    if (i < n) g_deg[i] = 1.0f;

    if (blockIdx.x == 0) {
        __shared__ float u[HDIM];
        int t = threadIdx.x;
        if (t < HDIM) {
            float acc = 0.f;
            #pragma unroll 8
            for (int j = 0; j < HDIM; ++j) acc += W2[t * HDIM + j] * fc_w[j];
            u[t] = acc;
        }
        __syncthreads();
        if (t < DIN) {
            float acc = 0.f;
            #pragma unroll 8
            for (int j = 0; j < HDIM; ++j) acc += W1[t * HDIM + j] * u[j];
            g_w[t] = acc;
        }
        if (t == 0) {
            float c1 = 0.f, c2 = 0.f;
            for (int j = 0; j < HDIM; ++j) { c1 += b1[j] * u[j]; c2 += b2[j] * fc_w[j]; }
            g_c1 = c1;
            g_c2 = c2 + fc_b[0];
        }
    }
}

// ---------------------------------------------------------------------------
// K1: deg[dst] += ew   -- 4 edges per thread, vectorized.
// ---------------------------------------------------------------------------
__global__ void k_deg_acc(const int* __restrict__ dst,
                          const float* __restrict__ ew, int E, int n) {
    int e4 = (blockIdx.x * blockDim.x + threadIdx.x) * 4;
    if (e4 + 3 < E) {
        int4   d = *(const int4*)(dst + e4);
        float4 w = *(const float4*)(ew + e4);
        if ((unsigned)d.x < (unsigned)n) atomicAdd(&g_deg[d.x], w.x);
        if ((unsigned)d.y < (unsigned)n) atomicAdd(&g_deg[d.y], w.y);
        if ((unsigned)d.z < (unsigned)n) atomicAdd(&g_deg[d.z], w.z);
        if ((unsigned)d.w < (unsigned)n) atomicAdd(&g_deg[d.w], w.w);
    } else {
        for (int e = e4; e < E; ++e) {
            unsigned d = (unsigned)dst[e];
            if (d < (unsigned)n) atomicAdd(&g_deg[d], ew[e]);
        }
    }
}

// ---------------------------------------------------------------------------
// K2: per node -- dis = rsqrt(deg); s = x.w; t = dis^2*s + c1 (prop1 self-loop)
// One warp processes 4 nodes: 4 independent LDG.128 per lane (MLP=4),
// 4 overlapping butterfly reductions, lanes 0..3 write nodes 0..3.
// ---------------------------------------------------------------------------
__global__ void k_node(const float* __restrict__ x, int n) {
    int warp = (blockIdx.x * blockDim.x + threadIdx.x) >> 5;
    int lane = threadIdx.x & 31;
    int base = warp * 4;
    if (base >= n) return;

    float4 wv = ((const float4*)g_w)[lane];

    float acc[4];
    if (base + 3 < n) {
        const float4* xr = (const float4*)(x + (size_t)base * DIN);
        float4 v0 = xr[lane];
        float4 v1 = xr[32 + lane];
        float4 v2 = xr[64 + lane];
        float4 v3 = xr[96 + lane];
        acc[0] = v0.x * wv.x + v0.y * wv.y + v0.z * wv.z + v0.w * wv.w;
        acc[1] = v1.x * wv.x + v1.y * wv.y + v1.z * wv.z + v1.w * wv.w;
        acc[2] = v2.x * wv.x + v2.y * wv.y + v2.z * wv.z + v2.w * wv.w;
        acc[3] = v3.x * wv.x + v3.y * wv.y + v3.z * wv.z + v3.w * wv.w;
    } else {
        #pragma unroll
        for (int k = 0; k < 4; ++k) {
            if (base + k < n) {
                const float4* xr = (const float4*)(x + (size_t)(base + k) * DIN);
                float4 v = xr[lane];
                acc[k] = v.x * wv.x + v.y * wv.y + v.z * wv.z + v.w * wv.w;
            } else {
                acc[k] = 0.f;
            }
        }
    }

    #pragma unroll
    for (int o = 16; o; o >>= 1) {
        acc[0] += __shfl_xor_sync(0xFFFFFFFFu, acc[0], o);
        acc[1] += __shfl_xor_sync(0xFFFFFFFFu, acc[1], o);
        acc[2] += __shfl_xor_sync(0xFFFFFFFFu, acc[2], o);
        acc[3] += __shfl_xor_sync(0xFFFFFFFFu, acc[3], o);
    }

    if (lane < 4 && base + lane < n) {
        int node = base + lane;
        float s = acc[lane];
        float deg = g_deg[node];
        float dis = deg > 0.f ? rsqrtf(fmaxf(deg, 1e-12f)) : 0.f;
        g_dis[node] = dis;
        g_s[node]   = s;
        g_t[node]   = dis * dis * s + g_c1;
    }
}

// ---------------------------------------------------------------------------
// K3/K4: edge propagation, 4 edges per thread.
//   acc[dst] += dis[src] * ew * dis[dst] * val[src]
// ---------------------------------------------------------------------------
template <int PASS>
__global__ void k_prop(const int* __restrict__ ei,
                       const float* __restrict__ ew, int E, int n) {
    const float* val = (PASS == 1) ? g_s : g_t;
    float*       acc = (PASS == 1) ? g_t : g_s;
    int e4 = (blockIdx.x * blockDim.x + threadIdx.x) * 4;
    if (e4 + 3 < E) {
        int4   s = *(const int4*)(ei + e4);
        int4   d = *(const int4*)(ei + (size_t)E + e4);
        float4 w = *(const float4*)(ew + e4);
        if ((unsigned)s.x < (unsigned)n && (unsigned)d.x < (unsigned)n)
            atomicAdd(&acc[d.x], g_dis[s.x] * w.x * g_dis[d.x] * val[s.x]);
        if ((unsigned)s.y < (unsigned)n && (unsigned)d.y < (unsigned)n)
            atomicAdd(&acc[d.y], g_dis[s.y] * w.y * g_dis[d.y] * val[s.y]);
        if ((unsigned)s.z < (unsigned)n && (unsigned)d.z < (unsigned)n)
            atomicAdd(&acc[d.z], g_dis[s.z] * w.z * g_dis[d.z] * val[s.z]);
        if ((unsigned)s.w < (unsigned)n && (unsigned)d.w < (unsigned)n)
            atomicAdd(&acc[d.w], g_dis[s.w] * w.w * g_dis[d.w] * val[s.w]);
    } else {
        for (int e = e4; e < E; ++e) {
            unsigned s = (unsigned)ei[e];
            unsigned d = (unsigned)ei[(size_t)E + e];
            if (s < (unsigned)n && d < (unsigned)n)
                atomicAdd(&acc[d], g_dis[s] * ew[e] * g_dis[d] * val[s]);
        }
    }
}

// ---------------------------------------------------------------------------
// K mid: s[n] = dis^2 * t[n] + c2  (prop2 self-loop + collapsed biases)
// ---------------------------------------------------------------------------
__global__ void k_mid(int n) {
    int i = blockIdx.x * blockDim.x + threadIdx.x;
    if (i < n) {
        float dis = g_dis[i];
        g_s[i] = dis * dis * g_t[i] + g_c2;
    }
}

// K out: out = rint(clip(s, 0, 10))  (round-half-even matches jnp.round)
__global__ void k_out(float* __restrict__ out, int n) {
    int i = blockIdx.x * blockDim.x + threadIdx.x;
    if (i < n) out[i] = rintf(fminf(fmaxf(g_s[i], 0.f), 10.f));
}

extern "C" void kernel_launch(void* const* d_in, const int* in_sizes, int n_in,
                              void* d_out, int out_size) {
    const float* x    = (const float*)d_in[0];
    const int*   ei   = (const int*)d_in[1];    // int32 [2, E]
    const float* ew   = (const float*)d_in[2];
    const float* W1   = (const float*)d_in[3];
    const float* b1   = (const float*)d_in[4];
    const float* W2   = (const float*)d_in[5];
    const float* b2   = (const float*)d_in[6];
    const float* fc_w = (const float*)d_in[7];
    const float* fc_b = (const float*)d_in[8];
    float*       out  = (float*)d_out;

    const int E = in_sizes[2];             // 1600000
    const int N = in_sizes[0] / DIN;       // 100000

    const int TB = 256;
    const int nb_nodes  = (N + TB - 1) / TB;
    const int nb_edges4 = ((E + 3) / 4 + TB - 1) / TB;
    const int nb_warps  = (((N + 3) / 4) * 32 + TB - 1) / TB;  // 4 nodes per warp

    k_init<<<nb_nodes, TB>>>(W1, b1, W2, b2, fc_w, fc_b, N);
    k_deg_acc<<<nb_edges4, TB>>>(ei + E, ew, E, N);
    k_node<<<nb_warps, TB>>>(x, N);
    k_prop<1><<<nb_edges4, TB>>>(ei, ew, E, N);
    k_mid<<<nb_nodes, TB>>>(N);
    k_prop<2><<<nb_edges4, TB>>>(ei, ew, E, N);
    k_out<<<nb_nodes, TB>>>(out, N);
}

// round 4
// speedup vs baseline: 1.3149x; 1.2606x over previous
#include <cuda_runtime.h>

#define N_NODES 100000
#define DIN     128
#define HDIM    64

// Scratch (device globals -- no allocation allowed in kernel_launch)
__device__ float g_deg[N_NODES];
__device__ float g_dis[N_NODES];
__device__ float g_p[N_NODES];     // dis[i] * val[i]  (current layer)
__device__ float g_acc[N_NODES];   // accumulator, init = p (self-loop folded)
__device__ __align__(16) float g_w[DIN];
__device__ float g_c1;
__device__ float g_c2;

// ---------------------------------------------------------------------------
// K0: fused init.  All blocks: deg[i] = 1 (self-loop weight).
// Block 0 additionally collapses weights:
//   u = W2 @ fc_w (64), w = W1 @ u (128), c1 = b1.u, c2 = b2.fc_w + fc_b
// ---------------------------------------------------------------------------
__global__ void k_init(const float* __restrict__ W1, const float* __restrict__ b1,
                       const float* __restrict__ W2, const float* __restrict__ b2,
                       const float* __restrict__ fc_w, const float* __restrict__ fc_b,
                       int n) {
    int i = blockIdx.x * blockDim.x + threadIdx.x;
    if (i < n) g_deg[i] = 1.0f;

    if (blockIdx.x == 0) {
        __shared__ float u[HDIM];
        int t = threadIdx.x;
        if (t < HDIM) {
            float acc = 0.f;
            #pragma unroll 8
            for (int j = 0; j < HDIM; ++j) acc += W2[t * HDIM + j] * fc_w[j];
            u[t] = acc;
        }
        __syncthreads();
        if (t < DIN) {
            float acc = 0.f;
            #pragma unroll 8
            for (int j = 0; j < HDIM; ++j) acc += W1[t * HDIM + j] * u[j];
            g_w[t] = acc;
        }
        if (t == 0) {
            float c1 = 0.f, c2 = 0.f;
            for (int j = 0; j < HDIM; ++j) { c1 += b1[j] * u[j]; c2 += b2[j] * fc_w[j]; }
            g_c1 = c1;
            g_c2 = c2 + fc_b[0];
        }
    }
}

// ---------------------------------------------------------------------------
// K1: deg[dst] += ew   -- 4 edges per thread, vectorized.
// ---------------------------------------------------------------------------
__global__ void k_deg_acc(const int* __restrict__ dst,
                          const float* __restrict__ ew, int E, int n) {
    int e4 = (blockIdx.x * blockDim.x + threadIdx.x) * 4;
    if (e4 + 3 < E) {
        int4   d = *(const int4*)(dst + e4);
        float4 w = *(const float4*)(ew + e4);
        if ((unsigned)d.x < (unsigned)n) atomicAdd(&g_deg[d.x], w.x);
        if ((unsigned)d.y < (unsigned)n) atomicAdd(&g_deg[d.y], w.y);
        if ((unsigned)d.z < (unsigned)n) atomicAdd(&g_deg[d.z], w.z);
        if ((unsigned)d.w < (unsigned)n) atomicAdd(&g_deg[d.w], w.w);
    } else {
        for (int e = e4; e < E; ++e) {
            unsigned d = (unsigned)dst[e];
            if (d < (unsigned)n) atomicAdd(&g_deg[d], ew[e]);
        }
    }
}

// ---------------------------------------------------------------------------
// K2: per node -- dis = rsqrt(deg); s = x.w; p = dis*s; acc = p (self-loop)
// One warp processes 4 nodes (MLP=4 on the x stream).
// ---------------------------------------------------------------------------
__global__ void k_node(const float* __restrict__ x, int n) {
    int warp = (blockIdx.x * blockDim.x + threadIdx.x) >> 5;
    int lane = threadIdx.x & 31;
    int base = warp * 4;
    if (base >= n) return;

    float4 wv = ((const float4*)g_w)[lane];

    float acc[4];
    if (base + 3 < n) {
        const float4* xr = (const float4*)(x + (size_t)base * DIN);
        float4 v0 = xr[lane];
        float4 v1 = xr[32 + lane];
        float4 v2 = xr[64 + lane];
        float4 v3 = xr[96 + lane];
        acc[0] = v0.x * wv.x + v0.y * wv.y + v0.z * wv.z + v0.w * wv.w;
        acc[1] = v1.x * wv.x + v1.y * wv.y + v1.z * wv.z + v1.w * wv.w;
        acc[2] = v2.x * wv.x + v2.y * wv.y + v2.z * wv.z + v2.w * wv.w;
        acc[3] = v3.x * wv.x + v3.y * wv.y + v3.z * wv.z + v3.w * wv.w;
    } else {
        #pragma unroll
        for (int k = 0; k < 4; ++k) {
            if (base + k < n) {
                const float4* xr = (const float4*)(x + (size_t)(base + k) * DIN);
                float4 v = xr[lane];
                acc[k] = v.x * wv.x + v.y * wv.y + v.z * wv.z + v.w * wv.w;
            } else {
                acc[k] = 0.f;
            }
        }
    }

    #pragma unroll
    for (int o = 16; o; o >>= 1) {
        acc[0] += __shfl_xor_sync(0xFFFFFFFFu, acc[0], o);
        acc[1] += __shfl_xor_sync(0xFFFFFFFFu, acc[1], o);
        acc[2] += __shfl_xor_sync(0xFFFFFFFFu, acc[2], o);
        acc[3] += __shfl_xor_sync(0xFFFFFFFFu, acc[3], o);
    }

    if (lane < 4 && base + lane < n) {
        int node = base + lane;
        float s = acc[lane];
        float deg = g_deg[node];
        float dis = deg > 0.f ? rsqrtf(fmaxf(deg, 1e-12f)) : 0.f;
        float p = dis * s;
        g_dis[node] = dis;
        g_p[node]   = p;
        g_acc[node] = p;     // self-loop term dis^2*s, dis applied later
    }
}

// ---------------------------------------------------------------------------
// K prop (both layers): acc[dst] += ew * p[src]
// One gather + one atomic per edge.  4 edges per thread.
// ---------------------------------------------------------------------------
__global__ void k_prop(const int* __restrict__ ei,
                       const float* __restrict__ ew, int E, int n) {
    int e4 = (blockIdx.x * blockDim.x + threadIdx.x) * 4;
    if (e4 + 3 < E) {
        int4   s = *(const int4*)(ei + e4);
        int4   d = *(const int4*)(ei + (size_t)E + e4);
        float4 w = *(const float4*)(ew + e4);
        if ((unsigned)s.x < (unsigned)n && (unsigned)d.x < (unsigned)n)
            atomicAdd(&g_acc[d.x], w.x * g_p[s.x]);
        if ((unsigned)s.y < (unsigned)n && (unsigned)d.y < (unsigned)n)
            atomicAdd(&g_acc[d.y], w.y * g_p[s.y]);
        if ((unsigned)s.z < (unsigned)n && (unsigned)d.z < (unsigned)n)
            atomicAdd(&g_acc[d.z], w.z * g_p[s.z]);
        if ((unsigned)s.w < (unsigned)n && (unsigned)d.w < (unsigned)n)
            atomicAdd(&g_acc[d.w], w.w * g_p[s.w]);
    } else {
        for (int e = e4; e < E; ++e) {
            unsigned s = (unsigned)ei[e];
            unsigned d = (unsigned)ei[(size_t)E + e];
            if (s < (unsigned)n && d < (unsigned)n)
                atomicAdd(&g_acc[d], ew[e] * g_p[s]);
        }
    }
}

// ---------------------------------------------------------------------------
// K mid: t = c1 + dis*acc;  p2 = dis*t;  acc = p2 (self-loop of layer 2)
// ---------------------------------------------------------------------------
__global__ void k_mid(int n) {
    int i = blockIdx.x * blockDim.x + threadIdx.x;
    if (i < n) {
        float dis = g_dis[i];
        float t   = fmaf(dis, g_acc[i], g_c1);
        float p2  = dis * t;
        g_p[i]   = p2;
        g_acc[i] = p2;
    }
}

// K out: out = rint(clip(c2 + dis*acc, 0, 10))  (round-half-even = jnp.round)
__global__ void k_out(float* __restrict__ out, int n) {
    int i = blockIdx.x * blockDim.x + threadIdx.x;
    if (i < n) {
        float v = fmaf(g_dis[i], g_acc[i], g_c2);
        out[i] = rintf(fminf(fmaxf(v, 0.f), 10.f));
    }
}

extern "C" void kernel_launch(void* const* d_in, const int* in_sizes, int n_in,
                              void* d_out, int out_size) {
    const float* x    = (const float*)d_in[0];
    const int*   ei   = (const int*)d_in[1];    // int32 [2, E]
    const float* ew   = (const float*)d_in[2];
    const float* W1   = (const float*)d_in[3];
    const float* b1   = (const float*)d_in[4];
    const float* W2   = (const float*)d_in[5];
    const float* b2   = (const float*)d_in[6];
    const float* fc_w = (const float*)d_in[7];
    const float* fc_b = (const float*)d_in[8];
    float*       out  = (float*)d_out;

    const int E = in_sizes[2];             // 1600000
    const int N = in_sizes[0] / DIN;       // 100000

    const int TB = 256;
    const int nb_nodes  = (N + TB - 1) / TB;
    const int nb_edges4 = ((E + 3) / 4 + TB - 1) / TB;
    const int nb_warps  = (((N + 3) / 4) * 32 + TB - 1) / TB;  // 4 nodes per warp

    k_init<<<nb_nodes, TB>>>(W1, b1, W2, b2, fc_w, fc_b, N);
    k_deg_acc<<<nb_edges4, TB>>>(ei + E, ew, E, N);
    k_node<<<nb_warps, TB>>>(x, N);
    k_prop<<<nb_edges4, TB>>>(ei, ew, E, N);
    k_mid<<<nb_nodes, TB>>>(N);
    k_prop<<<nb_edges4, TB>>>(ei, ew, E, N);
    k_out<<<nb_nodes, TB>>>(out, N);
}